// round 16
// baseline (speedup 1.0000x reference)
#include <cuda_runtime.h>
#include <cuda.h>
#include <cuda_bf16.h>
#include <stdint.h>

#define DI __device__ __forceinline__

// ---------------- problem constants ----------------
static constexpr int    NDIM     = 4096;
static constexpr float  INVSCALE = 1.0f / (31.75f * 127.0f);   // 1/(sx*sw)

// ---------------- GEMM tiling (bf16 HMMA + TMA, warp-specialized) ----------------
static constexpr int BM = 128, BN = 128, BK = 64;
static constexpr int STAGES = 3;
static constexpr int KT = NDIM / BK;                    // 64 k-iterations
static constexpr int A_STAGE_B = BM * 128;              // 16384 (128 rows x 128B)
static constexpr int B_STAGE_B = BN * 128;              // 16384
static constexpr int STAGE_B   = A_STAGE_B + B_STAGE_B; // 32768
static constexpr int SMEM_HDR  = 1024;
static constexpr int SMEM_TOTAL = SMEM_HDR + STAGES * STAGE_B;  // 99328
static constexpr int NCONS = 256;                       // consumer threads

// ---------------- device scratch (allocation-free rule) ----------------
__device__ __nv_bfloat16 g_Xq[(size_t)NDIM * NDIM];   // quantized activations (integer-valued bf16)
__device__ __nv_bfloat16 g_Wq[(size_t)NDIM * NDIM];   // quantized weights (integer-valued bf16)
__device__ float         g_badd[NDIM];                // epilogue bias term

// ---------------- PTX helpers ----------------
DI uint32_t smem_u32(const void* p) {
    uint32_t a;
    asm("{ .reg .u64 t; cvta.to.shared.u64 t, %1; cvt.u32.u64 %0, t; }" : "=r"(a) : "l"(p));
    return a;
}
DI void ldsm4(uint32_t* r, uint32_t addr) {
    asm volatile("ldmatrix.sync.aligned.m8n8.x4.shared.b16 {%0,%1,%2,%3}, [%4];"
                 : "=r"(r[0]), "=r"(r[1]), "=r"(r[2]), "=r"(r[3]) : "r"(addr));
}
DI void mma16816(float* c, const uint32_t* a, uint32_t b0, uint32_t b1) {
    asm volatile(
        "mma.sync.aligned.m16n8k16.row.col.f32.bf16.bf16.f32 "
        "{%0,%1,%2,%3}, {%4,%5,%6,%7}, {%8,%9}, {%0,%1,%2,%3};"
        : "+f"(c[0]), "+f"(c[1]), "+f"(c[2]), "+f"(c[3])
        : "r"(a[0]), "r"(a[1]), "r"(a[2]), "r"(a[3]), "r"(b0), "r"(b1));
}
// SW128 swizzled byte offset: 128B rows, 16B chunk c in [0,8)
DI uint32_t sw_off(int row, int c) {
    return (uint32_t)(row * 128 + ((c ^ (row & 7)) << 4));
}
DI void mbar_init(uint32_t a, uint32_t cnt) {
    asm volatile("mbarrier.init.shared.b64 [%0], %1;" :: "r"(a), "r"(cnt) : "memory");
}
DI void mbar_expect(uint32_t a, uint32_t bytes) {
    asm volatile("mbarrier.arrive.expect_tx.shared.b64 _, [%0], %1;"
                 :: "r"(a), "r"(bytes) : "memory");
}
DI void mbar_arrive_rel(uint32_t a) {
    asm volatile("mbarrier.arrive.release.cta.shared::cta.b64 _, [%0];" :: "r"(a) : "memory");
}
DI void mbar_wait(uint32_t a, uint32_t parity) {
    asm volatile(
        "{\n\t.reg .pred P;\n"
        "WL_%=:\n\t"
        "mbarrier.try_wait.parity.acquire.cta.shared::cta.b64 P, [%0], %1, 0x989680;\n\t"
        "@P bra WD_%=;\n\t"
        "bra WL_%=;\n"
        "WD_%=:\n\t}"
        :: "r"(a), "r"(parity) : "memory");
}
DI void tma2d(uint32_t dst, const CUtensorMap* tm, int cx, int cy, uint32_t mbar) {
    asm volatile(
        "cp.async.bulk.tensor.2d.shared::cluster.global.tile.mbarrier::complete_tx::bytes "
        "[%0], [%1, {%2, %3}], [%4];"
        :: "r"(dst), "l"(tm), "r"(cx), "r"(cy), "r"(mbar) : "memory");
}
DI void tm_prefetch(const CUtensorMap* tm) {
    asm volatile("prefetch.tensormap [%0];" :: "l"(tm));
}
DI void l2_prefetch(const void* p) {
    asm volatile("prefetch.global.L2 [%0];" :: "l"(p));
}
DI float2 ldg_cs_f2(const float* p) {
    float2 v;
    asm volatile("ld.global.nc.cs.v2.f32 {%0, %1}, [%2];"
                 : "=f"(v.x), "=f"(v.y) : "l"(p));
    return v;
}
DI void stg_cs_f2(float* p, float2 v) {
    asm volatile("st.global.cs.v2.f32 [%0], {%1, %2};"
                 :: "l"(p), "f"(v.x), "f"(v.y) : "memory");
}

// ---------------- fused quantize kernel (X, W, and bias in ONE launch) ----------------
// 16 floats per thread: 4x float4 loads, 1x uint4 store. blockIdx.y: 0 = X, 1 = W.
// Bias (4096 floats) handled by the first 16 blocks of the X pass.
__global__ void quant_all_kernel(const float4* __restrict__ x,
                                 const float4* __restrict__ w,
                                 const float* __restrict__ b) {
    const int which = blockIdx.y;
    const float clip  = which ? 1.0f   : 4.0f;
    const float scale = which ? 127.0f : 31.75f;
    const float4* src = which ? w : x;
    size_t i = (size_t)blockIdx.x * blockDim.x + threadIdx.x;

    if (which == 0 && blockIdx.x < 16) {
        const int bi = blockIdx.x * 256 + threadIdx.x;
        float q = rintf(fminf(1.0f, fmaxf(-1.0f, b[bi])) * 127.0f);
        g_badd[bi] = 32.0f * q * INVSCALE;   // quantized ones-column (=32) * quantized bias
    }

    uint32_t words[8];
#pragma unroll
    for (int j = 0; j < 4; ++j) {
        float4 v = src[i * 4 + j];
        float a0 = rintf(fminf(clip, fmaxf(-clip, v.x)) * scale);
        float a1 = rintf(fminf(clip, fmaxf(-clip, v.y)) * scale);
        float a2 = rintf(fminf(clip, fmaxf(-clip, v.z)) * scale);
        float a3 = rintf(fminf(clip, fmaxf(-clip, v.w)) * scale);
        __nv_bfloat162 p0 = __floats2bfloat162_rn(a0, a1);
        __nv_bfloat162 p1 = __floats2bfloat162_rn(a2, a3);
        words[2 * j + 0] = *reinterpret_cast<uint32_t*>(&p0);
        words[2 * j + 1] = *reinterpret_cast<uint32_t*>(&p1);
    }
    uint4* dst = reinterpret_cast<uint4*>(which ? g_Wq : g_Xq);
    dst[i * 2 + 0] = make_uint4(words[0], words[1], words[2], words[3]);
    dst[i * 2 + 1] = make_uint4(words[4], words[5], words[6], words[7]);
}

// ---------------- GEMM: producer warp (TMA) + 8 consumer warps (HMMA) ----------------
__global__ __launch_bounds__(288, 2)
void gemm_kernel(const __grid_constant__ CUtensorMap tmA,
                 const __grid_constant__ CUtensorMap tmB,
                 const float* __restrict__ noise, float* __restrict__ out) {
    extern __shared__ __align__(1024) char smem[];
    const uint32_t sb = smem_u32(smem);
    const int tid  = threadIdx.x;
    const int lane = tid & 31;

    const uint32_t FULL  = sb;       // full[s]  at sb + 8*s
    const uint32_t EMPTY = sb + 24;  // empty[s] at sb + 24 + 8*s

    if (tid == 0) {
#pragma unroll
        for (int s = 0; s < STAGES; ++s) {
            mbar_init(FULL + 8u * s, 1);
            mbar_init(EMPTY + 8u * s, NCONS);
        }
        asm volatile("fence.mbarrier_init.release.cluster;" ::: "memory");
    }
    __syncthreads();

    const int tileM = blockIdx.y, tileN = blockIdx.x;

    if (tid >= NCONS) {
        // ================= producer warp =================
        if (lane == 0) {
            tm_prefetch(&tmA);
            tm_prefetch(&tmB);
#pragma unroll
            for (int f = 0; f < STAGES; ++f) {
                const uint32_t a_s = sb + SMEM_HDR + f * STAGE_B;
                mbar_expect(FULL + 8u * f, (uint32_t)STAGE_B);
                tma2d(a_s,             &tmA, f * BK, tileM * BM, FULL + 8u * f);
                tma2d(a_s + A_STAGE_B, &tmB, f * BK, tileN * BN, FULL + 8u * f);
            }
            int s = 0, php = 0;
            for (int f = STAGES; f < KT; ++f) {
                const uint32_t a_s = sb + SMEM_HDR + s * STAGE_B;
                mbar_wait(EMPTY + 8u * s, (uint32_t)php);
                mbar_expect(FULL + 8u * s, (uint32_t)STAGE_B);
                tma2d(a_s,             &tmA, f * BK, tileM * BM, FULL + 8u * s);
                tma2d(a_s + A_STAGE_B, &tmB, f * BK, tileN * BN, FULL + 8u * s);
                if (++s == STAGES) { s = 0; php ^= 1; }
            }
        }
        // All TMAs issued; consumers still have ~STAGES iterations left.
        // Warm L2 with this CTA's epilogue noise tile (128 rows x 512B = 512 x 128B lines).
        {
            const float* nbase = noise + (size_t)(tileM * BM) * NDIM + (size_t)tileN * BN;
#pragma unroll 4
            for (int r = lane; r < BM; r += 32) {
                const float* row = nbase + (size_t)r * NDIM;
                l2_prefetch(row);
                l2_prefetch(row + 32);
                l2_prefetch(row + 64);
                l2_prefetch(row + 96);
            }
        }
        return;
    }

    // ================= consumer warps =================
    const int warp  = tid >> 5;
    const int warpM = warp >> 1;     // 0..3, 32 rows each
    const int warpN = warp & 1;      // 0..1, 64 cols each

    float c[2][8][4];
#pragma unroll
    for (int i = 0; i < 2; ++i)
#pragma unroll
        for (int j = 0; j < 8; ++j)
#pragma unroll
            for (int k = 0; k < 4; ++k) c[i][j][k] = 0.0f;

    // per-lane swizzled ldmatrix base offsets (swizzle invariant under row+16 => +2048B)
    const int lrow = lane & 15;
    const int csel = lane >> 4;
    uint32_t offA0[4], offB0[4];
    {
        const int rA = warpM * 32 + lrow;
        const int rB = warpN * 64 + lrow;
#pragma unroll
        for (int kk = 0; kk < 4; ++kk) {
            offA0[kk] = sw_off(rA, (kk << 1) | csel);
            offB0[kk] = sw_off(rB, (kk << 1) | csel);
        }
    }

    int s = 0, ph = 0;
    for (int kt = 0; kt < KT; ++kt) {
        const uint32_t a_s = sb + SMEM_HDR + s * STAGE_B;
        const uint32_t b_s = a_s + A_STAGE_B;

        mbar_wait(FULL + 8u * s, (uint32_t)ph);

#pragma unroll
        for (int kk = 0; kk < 4; ++kk) {
            uint32_t a[2][4], b[4][4];
            ldsm4(a[0], a_s + offA0[kk]);
            ldsm4(a[1], a_s + offA0[kk] + 2048);
#pragma unroll
            for (int q = 0; q < 4; ++q)
                ldsm4(b[q], b_s + offB0[kk] + (uint32_t)(q * 2048));
            // all smem reads of this stage issued after kk==3's burst;
            // release-arrive orders them before the producer's TMA overwrite.
            if (kk == 3) mbar_arrive_rel(EMPTY + 8u * s);
#pragma unroll
            for (int q = 0; q < 4; ++q) {
                mma16816(c[0][2 * q + 0], a[0], b[q][0], b[q][2]);
                mma16816(c[0][2 * q + 1], a[0], b[q][1], b[q][3]);
                mma16816(c[1][2 * q + 0], a[1], b[q][0], b[q][2]);
                mma16816(c[1][2 * q + 1], a[1], b[q][1], b[q][3]);
            }
        }

        if (++s == STAGES) { s = 0; ph ^= 1; }
    }

    // ---- fused epilogue: out = acc*INV + badd[n] + 0.01*noise ----
    // noise was L2-prefetched by the producer warp; use streaming (evict-first)
    // loads/stores so the epilogue doesn't evict Xq/Wq from L2.
    const int mBase = tileM * BM + warpM * 32 + (lane >> 2);
    const int nBase = tileN * BN + warpN * 64 + (lane & 3) * 2;
#pragma unroll
    for (int mt = 0; mt < 2; ++mt) {
#pragma unroll
        for (int nt = 0; nt < 8; ++nt) {
#pragma unroll
            for (int half = 0; half < 2; ++half) {
                const int m = mBase + mt * 16 + half * 8;
                const int n = nBase + nt * 8;
                const size_t off = (size_t)m * NDIM + n;
                float2 nz = ldg_cs_f2(noise + off);
                float2 bd = *reinterpret_cast<const float2*>(g_badd + n);
                float2 o;
                o.x = fmaf(c[mt][nt][2 * half + 0], INVSCALE, fmaf(0.01f, nz.x, bd.x));
                o.y = fmaf(c[mt][nt][2 * half + 1], INVSCALE, fmaf(0.01f, nz.y, bd.y));
                stg_cs_f2(out + off, o);
            }
        }
    }
}

// ---------------- launch ----------------
typedef CUresult (*PFN_tmEncode)(
    CUtensorMap*, CUtensorMapDataType, cuuint32_t, void*,
    const cuuint64_t*, const cuuint64_t*, const cuuint32_t*, const cuuint32_t*,
    CUtensorMapInterleave, CUtensorMapSwizzle, CUtensorMapL2promotion,
    CUtensorMapFloatOOBfill);

extern "C" void kernel_launch(void* const* d_in, const int* in_sizes, int n_in,
                              void* d_out, int out_size) {
    const float* x  = (const float*)d_in[0];   // tensor  [4096,4096]
    const float* w  = (const float*)d_in[1];   // weights [4096,4096]
    const float* b  = (const float*)d_in[2];   // biases  [4096]
    const float* nz = (const float*)d_in[3];   // noise   [4096,4096]
    float* out = (float*)d_out;

    // fused quantization (X + W + bias): 16 floats per thread
    dim3 qgrid((NDIM * NDIM / 16) / 256, 2);   // (4096, 2)
    quant_all_kernel<<<qgrid, 256>>>((const float4*)x, (const float4*)w, b);

    // build tensormaps (host-side, pure; no allocation)
    void* encFn = nullptr;
    cudaDriverEntryPointQueryResult qres;
    cudaGetDriverEntryPoint("cuTensorMapEncodeTiled", &encFn, cudaEnableDefault, &qres);
    PFN_tmEncode enc = (PFN_tmEncode)encFn;

    void *xq_ptr = nullptr, *wq_ptr = nullptr;
    cudaGetSymbolAddress(&xq_ptr, g_Xq);
    cudaGetSymbolAddress(&wq_ptr, g_Wq);

    cuuint64_t dims[2]    = {(cuuint64_t)NDIM, (cuuint64_t)NDIM};
    cuuint64_t strides[1] = {(cuuint64_t)NDIM * 2};
    cuuint32_t box[2]     = {(cuuint32_t)BK, (cuuint32_t)BM};   // 64 elems x 128 rows
    cuuint32_t estr[2]    = {1, 1};

    CUtensorMap tmA, tmB;
    enc(&tmA, CU_TENSOR_MAP_DATA_TYPE_BFLOAT16, 2, xq_ptr, dims, strides, box, estr,
        CU_TENSOR_MAP_INTERLEAVE_NONE, CU_TENSOR_MAP_SWIZZLE_128B,
        CU_TENSOR_MAP_L2_PROMOTION_L2_128B, CU_TENSOR_MAP_FLOAT_OOB_FILL_NONE);
    enc(&tmB, CU_TENSOR_MAP_DATA_TYPE_BFLOAT16, 2, wq_ptr, dims, strides, box, estr,
        CU_TENSOR_MAP_INTERLEAVE_NONE, CU_TENSOR_MAP_SWIZZLE_128B,
        CU_TENSOR_MAP_L2_PROMOTION_L2_128B, CU_TENSOR_MAP_FLOAT_OOB_FILL_NONE);

    cudaFuncSetAttribute(gemm_kernel, cudaFuncAttributeMaxDynamicSharedMemorySize, SMEM_TOTAL);
    dim3 grid(NDIM / BN, NDIM / BM);            // 32 x 32 = 1024 CTAs
    gemm_kernel<<<grid, 288, SMEM_TOTAL>>>(tmA, tmB, nz, out);
}

// round 17
// speedup vs baseline: 1.0372x; 1.0372x over previous
#include <cuda_runtime.h>
#include <cuda.h>
#include <cuda_bf16.h>
#include <stdint.h>

#define DI __device__ __forceinline__

// ---------------- problem constants ----------------
static constexpr int    NDIM     = 4096;
static constexpr float  INVSCALE = 1.0f / (31.75f * 127.0f);   // 1/(sx*sw)

// ---------------- GEMM tiling (bf16 HMMA + TMA, warp-specialized) ----------------
static constexpr int BM = 128, BN = 128, BK = 64;
static constexpr int STAGES = 3;
static constexpr int KT = NDIM / BK;                    // 64 k-iterations
static constexpr int A_STAGE_B = BM * 128;              // 16384 (128 rows x 128B)
static constexpr int B_STAGE_B = BN * 128;              // 16384
static constexpr int STAGE_B   = A_STAGE_B + B_STAGE_B; // 32768
static constexpr int SMEM_HDR  = 1024;
static constexpr int SMEM_TOTAL = SMEM_HDR + STAGES * STAGE_B;  // 99328
static constexpr int NCONS = 256;                       // consumer threads

// ---------------- device scratch (allocation-free rule) ----------------
__device__ __nv_bfloat16 g_Xq[(size_t)NDIM * NDIM];   // quantized activations (integer-valued bf16)
__device__ __nv_bfloat16 g_Wq[(size_t)NDIM * NDIM];   // quantized weights (integer-valued bf16)
__device__ float         g_badd[NDIM];                // epilogue bias term

// ---------------- PTX helpers ----------------
DI uint32_t smem_u32(const void* p) {
    uint32_t a;
    asm("{ .reg .u64 t; cvta.to.shared.u64 t, %1; cvt.u32.u64 %0, t; }" : "=r"(a) : "l"(p));
    return a;
}
DI void ldsm4(uint32_t* r, uint32_t addr) {
    asm volatile("ldmatrix.sync.aligned.m8n8.x4.shared.b16 {%0,%1,%2,%3}, [%4];"
                 : "=r"(r[0]), "=r"(r[1]), "=r"(r[2]), "=r"(r[3]) : "r"(addr));
}
DI void mma16816(float* c, const uint32_t* a, uint32_t b0, uint32_t b1) {
    asm volatile(
        "mma.sync.aligned.m16n8k16.row.col.f32.bf16.bf16.f32 "
        "{%0,%1,%2,%3}, {%4,%5,%6,%7}, {%8,%9}, {%0,%1,%2,%3};"
        : "+f"(c[0]), "+f"(c[1]), "+f"(c[2]), "+f"(c[3])
        : "r"(a[0]), "r"(a[1]), "r"(a[2]), "r"(a[3]), "r"(b0), "r"(b1));
}
// SW128 swizzled byte offset: 128B rows, 16B chunk c in [0,8)
DI uint32_t sw_off(int row, int c) {
    return (uint32_t)(row * 128 + ((c ^ (row & 7)) << 4));
}
DI void mbar_init(uint32_t a, uint32_t cnt) {
    asm volatile("mbarrier.init.shared.b64 [%0], %1;" :: "r"(a), "r"(cnt) : "memory");
}
DI void mbar_expect(uint32_t a, uint32_t bytes) {
    asm volatile("mbarrier.arrive.expect_tx.shared.b64 _, [%0], %1;"
                 :: "r"(a), "r"(bytes) : "memory");
}
DI void mbar_arrive(uint32_t a) {
    asm volatile("mbarrier.arrive.shared.b64 _, [%0];" :: "r"(a) : "memory");
}
DI void mbar_wait(uint32_t a, uint32_t parity) {
    asm volatile(
        "{\n\t.reg .pred P;\n"
        "WL_%=:\n\t"
        "mbarrier.try_wait.parity.acquire.cta.shared::cta.b64 P, [%0], %1, 0x989680;\n\t"
        "@P bra WD_%=;\n\t"
        "bra WL_%=;\n"
        "WD_%=:\n\t}"
        :: "r"(a), "r"(parity) : "memory");
}
DI void tma2d(uint32_t dst, const CUtensorMap* tm, int cx, int cy, uint32_t mbar) {
    asm volatile(
        "cp.async.bulk.tensor.2d.shared::cluster.global.tile.mbarrier::complete_tx::bytes "
        "[%0], [%1, {%2, %3}], [%4];"
        :: "r"(dst), "l"(tm), "r"(cx), "r"(cy), "r"(mbar) : "memory");
}

// ---------------- fused quantize kernel (X, W, and bias in ONE launch) ----------------
// 16 floats per thread: 4x float4 loads, 1x uint4 store. blockIdx.y: 0 = X, 1 = W.
// Bias (4096 floats) handled by the first 16 blocks of the X pass.
__global__ void quant_all_kernel(const float4* __restrict__ x,
                                 const float4* __restrict__ w,
                                 const float* __restrict__ b) {
    const int which = blockIdx.y;
    const float clip  = which ? 1.0f   : 4.0f;
    const float scale = which ? 127.0f : 31.75f;
    const float4* src = which ? w : x;
    size_t i = (size_t)blockIdx.x * blockDim.x + threadIdx.x;

    if (which == 0 && blockIdx.x < 16) {
        const int bi = blockIdx.x * 256 + threadIdx.x;
        float q = rintf(fminf(1.0f, fmaxf(-1.0f, b[bi])) * 127.0f);
        g_badd[bi] = 32.0f * q * INVSCALE;   // quantized ones-column (=32) * quantized bias
    }

    uint32_t words[8];
#pragma unroll
    for (int j = 0; j < 4; ++j) {
        float4 v = src[i * 4 + j];
        float a0 = rintf(fminf(clip, fmaxf(-clip, v.x)) * scale);
        float a1 = rintf(fminf(clip, fmaxf(-clip, v.y)) * scale);
        float a2 = rintf(fminf(clip, fmaxf(-clip, v.z)) * scale);
        float a3 = rintf(fminf(clip, fmaxf(-clip, v.w)) * scale);
        __nv_bfloat162 p0 = __floats2bfloat162_rn(a0, a1);
        __nv_bfloat162 p1 = __floats2bfloat162_rn(a2, a3);
        words[2 * j + 0] = *reinterpret_cast<uint32_t*>(&p0);
        words[2 * j + 1] = *reinterpret_cast<uint32_t*>(&p1);
    }
    uint4* dst = reinterpret_cast<uint4*>(which ? g_Wq : g_Xq);
    dst[i * 2 + 0] = make_uint4(words[0], words[1], words[2], words[3]);
    dst[i * 2 + 1] = make_uint4(words[4], words[5], words[6], words[7]);
}

// ---------------- GEMM: producer warp (TMA) + 8 consumer warps (HMMA) ----------------
// (round-7 configuration verbatim — best measured GEMM: 314.6 us)
__global__ __launch_bounds__(288, 2)
void gemm_kernel(const __grid_constant__ CUtensorMap tmA,
                 const __grid_constant__ CUtensorMap tmB,
                 const float* __restrict__ noise, float* __restrict__ out) {
    extern __shared__ __align__(1024) char smem[];
    const uint32_t sb = smem_u32(smem);
    const int tid  = threadIdx.x;
    const int lane = tid & 31;

    const uint32_t FULL  = sb;       // full[s]  at sb + 8*s
    const uint32_t EMPTY = sb + 24;  // empty[s] at sb + 24 + 8*s

    if (tid == 0) {
#pragma unroll
        for (int s = 0; s < STAGES; ++s) {
            mbar_init(FULL + 8u * s, 1);
            mbar_init(EMPTY + 8u * s, NCONS);
        }
        asm volatile("fence.mbarrier_init.release.cluster;" ::: "memory");
    }
    __syncthreads();

    const int tileM = blockIdx.y, tileN = blockIdx.x;

    if (tid >= NCONS) {
        // ================= producer warp (lane 0 only) =================
        if (lane == 0) {
#pragma unroll
            for (int f = 0; f < STAGES; ++f) {
                const uint32_t a_s = sb + SMEM_HDR + f * STAGE_B;
                mbar_expect(FULL + 8u * f, (uint32_t)STAGE_B);
                tma2d(a_s,             &tmA, f * BK, tileM * BM, FULL + 8u * f);
                tma2d(a_s + A_STAGE_B, &tmB, f * BK, tileN * BN, FULL + 8u * f);
            }
            int s = 0, php = 0;
            for (int f = STAGES; f < KT; ++f) {
                const uint32_t a_s = sb + SMEM_HDR + s * STAGE_B;
                mbar_wait(EMPTY + 8u * s, (uint32_t)php);
                mbar_expect(FULL + 8u * s, (uint32_t)STAGE_B);
                tma2d(a_s,             &tmA, f * BK, tileM * BM, FULL + 8u * s);
                tma2d(a_s + A_STAGE_B, &tmB, f * BK, tileN * BN, FULL + 8u * s);
                if (++s == STAGES) { s = 0; php ^= 1; }
            }
        }
        return;
    }

    // ================= consumer warps =================
    const int warp  = tid >> 5;
    const int warpM = warp >> 1;     // 0..3, 32 rows each
    const int warpN = warp & 1;      // 0..1, 64 cols each

    float c[2][8][4];
#pragma unroll
    for (int i = 0; i < 2; ++i)
#pragma unroll
        for (int j = 0; j < 8; ++j)
#pragma unroll
            for (int k = 0; k < 4; ++k) c[i][j][k] = 0.0f;

    // per-lane swizzled ldmatrix base offsets (swizzle invariant under row+16 => +2048B)
    const int lrow = lane & 15;
    const int csel = lane >> 4;
    uint32_t offA0[4], offB0[4];
    {
        const int rA = warpM * 32 + lrow;
        const int rB = warpN * 64 + lrow;
#pragma unroll
        for (int kk = 0; kk < 4; ++kk) {
            offA0[kk] = sw_off(rA, (kk << 1) | csel);
            offB0[kk] = sw_off(rB, (kk << 1) | csel);
        }
    }

    int s = 0, ph = 0;
    for (int kt = 0; kt < KT; ++kt) {
        const uint32_t a_s = sb + SMEM_HDR + s * STAGE_B;
        const uint32_t b_s = a_s + A_STAGE_B;

        mbar_wait(FULL + 8u * s, (uint32_t)ph);

#pragma unroll
        for (int kk = 0; kk < 4; ++kk) {
            uint32_t a[2][4], b[4][4];
            ldsm4(a[0], a_s + offA0[kk]);
            ldsm4(a[1], a_s + offA0[kk] + 2048);
#pragma unroll
            for (int q = 0; q < 4; ++q)
                ldsm4(b[q], b_s + offB0[kk] + (uint32_t)(q * 2048));
#pragma unroll
            for (int q = 0; q < 4; ++q) {
                mma16816(c[0][2 * q + 0], a[0], b[q][0], b[q][2]);
                mma16816(c[0][2 * q + 1], a[0], b[q][1], b[q][3]);
                mma16816(c[1][2 * q + 0], a[1], b[q][0], b[q][2]);
                mma16816(c[1][2 * q + 1], a[1], b[q][1], b[q][3]);
            }
        }

        mbar_arrive(EMPTY + 8u * s);
        if (++s == STAGES) { s = 0; ph ^= 1; }
    }

    // ---- fused epilogue: out = acc*INV + badd[n] + 0.01*noise ----
    const int mBase = tileM * BM + warpM * 32 + (lane >> 2);
    const int nBase = tileN * BN + warpN * 64 + (lane & 3) * 2;
#pragma unroll
    for (int mt = 0; mt < 2; ++mt) {
#pragma unroll
        for (int nt = 0; nt < 8; ++nt) {
#pragma unroll
            for (int half = 0; half < 2; ++half) {
                const int m = mBase + mt * 16 + half * 8;
                const int n = nBase + nt * 8;
                const size_t off = (size_t)m * NDIM + n;
                float2 nz = *reinterpret_cast<const float2*>(noise + off);
                float2 bd = *reinterpret_cast<const float2*>(g_badd + n);
                float2 o;
                o.x = fmaf(c[mt][nt][2 * half + 0], INVSCALE, fmaf(0.01f, nz.x, bd.x));
                o.y = fmaf(c[mt][nt][2 * half + 1], INVSCALE, fmaf(0.01f, nz.y, bd.y));
                *reinterpret_cast<float2*>(out + off) = o;
            }
        }
    }
}

// ---------------- launch ----------------
typedef CUresult (*PFN_tmEncode)(
    CUtensorMap*, CUtensorMapDataType, cuuint32_t, void*,
    const cuuint64_t*, const cuuint64_t*, const cuuint32_t*, const cuuint32_t*,
    CUtensorMapInterleave, CUtensorMapSwizzle, CUtensorMapL2promotion,
    CUtensorMapFloatOOBfill);

extern "C" void kernel_launch(void* const* d_in, const int* in_sizes, int n_in,
                              void* d_out, int out_size) {
    const float* x  = (const float*)d_in[0];   // tensor  [4096,4096]
    const float* w  = (const float*)d_in[1];   // weights [4096,4096]
    const float* b  = (const float*)d_in[2];   // biases  [4096]
    const float* nz = (const float*)d_in[3];   // noise   [4096,4096]
    float* out = (float*)d_out;

    // fused quantization (X + W + bias): 16 floats per thread, single launch
    dim3 qgrid((NDIM * NDIM / 16) / 256, 2);   // (4096, 2)
    quant_all_kernel<<<qgrid, 256>>>((const float4*)x, (const float4*)w, b);

    // build tensormaps (host-side, pure; no allocation)
    void* encFn = nullptr;
    cudaDriverEntryPointQueryResult qres;
    cudaGetDriverEntryPoint("cuTensorMapEncodeTiled", &encFn, cudaEnableDefault, &qres);
    PFN_tmEncode enc = (PFN_tmEncode)encFn;

    void *xq_ptr = nullptr, *wq_ptr = nullptr;
    cudaGetSymbolAddress(&xq_ptr, g_Xq);
    cudaGetSymbolAddress(&wq_ptr, g_Wq);

    cuuint64_t dims[2]    = {(cuuint64_t)NDIM, (cuuint64_t)NDIM};
    cuuint64_t strides[1] = {(cuuint64_t)NDIM * 2};
    cuuint32_t box[2]     = {(cuuint32_t)BK, (cuuint32_t)BM};   // 64 elems x 128 rows
    cuuint32_t estr[2]    = {1, 1};

    CUtensorMap tmA, tmB;
    enc(&tmA, CU_TENSOR_MAP_DATA_TYPE_BFLOAT16, 2, xq_ptr, dims, strides, box, estr,
        CU_TENSOR_MAP_INTERLEAVE_NONE, CU_TENSOR_MAP_SWIZZLE_128B,
        CU_TENSOR_MAP_L2_PROMOTION_L2_128B, CU_TENSOR_MAP_FLOAT_OOB_FILL_NONE);
    enc(&tmB, CU_TENSOR_MAP_DATA_TYPE_BFLOAT16, 2, wq_ptr, dims, strides, box, estr,
        CU_TENSOR_MAP_INTERLEAVE_NONE, CU_TENSOR_MAP_SWIZZLE_128B,
        CU_TENSOR_MAP_L2_PROMOTION_L2_128B, CU_TENSOR_MAP_FLOAT_OOB_FILL_NONE);

    cudaFuncSetAttribute(gemm_kernel, cudaFuncAttributeMaxDynamicSharedMemorySize, SMEM_TOTAL);
    dim3 grid(NDIM / BN, NDIM / BM);            // 32 x 32 = 1024 CTAs
    gemm_kernel<<<grid, 288, SMEM_TOTAL>>>(tmA, tmB, nz, out);
}